// round 3
// baseline (speedup 1.0000x reference)
#include <cuda_runtime.h>

#define BATCH 8
#define HH 512
#define WW 512
#define NPIX (HH * WW)
#define NTOT (BATCH * NPIX)

// ---------------------------------------------------------------------------
// Compile-time parsing of the binary endpoint kernels (bit i*k+j = ker[i][j]).
// ---------------------------------------------------------------------------
__host__ __device__ constexpr unsigned long long kbits(const char* s) {
    unsigned long long m = 0;
    for (int i = 0; s[i]; ++i)
        if (s[i] == '1') m |= (1ull << i);
    return m;
}

// ---------------------------------------------------------------------------
// Scratch (allocation-free: __device__ globals)
// ---------------------------------------------------------------------------
__device__ float g_bufP1[NTOT];
__device__ float g_bufG1[NTOT];
__device__ float g_bufP2[NTOT];
__device__ float g_bufG2[NTOT];
__device__ float g_cmax[4];   // erosion conv maxima: P1,G1,P2,G2
__device__ float g_lm[6];     // level tensor maxima: P0,G0,P1,G1,P2,G2
__device__ double g_loss;

__device__ __forceinline__ const float* pick(int sel, const float* pred, const float* gt) {
    switch (sel) {
        case 0: return pred;
        case 1: return gt;
        case 2: return g_bufP1;
        case 3: return g_bufG1;
        case 4: return g_bufP2;
        default: return g_bufG2;
    }
}
__device__ __forceinline__ float* pick_buf(int sel) {
    switch (sel) {
        case 0: return g_bufP1;
        case 1: return g_bufG1;
        case 2: return g_bufP2;
        default: return g_bufG2;
    }
}

__device__ __forceinline__ float sigm(float x) {
    return __fdividef(1.0f, 1.0f + __expf(-x));
}

__device__ __forceinline__ float endpoint_sig(float nc) {
    float z = -10.0f * (nc - 1.0f);
    z = fminf(10.0f, fmaxf(-10.0f, z));
    return sigm(z);
}

// ---------------------------------------------------------------------------
// Block reductions (256 threads)
// ---------------------------------------------------------------------------
__device__ __forceinline__ float blockReduceSum(float v) {
    __shared__ float sh[8];
#pragma unroll
    for (int o = 16; o > 0; o >>= 1) v += __shfl_down_sync(0xffffffffu, v, o);
    int lane = threadIdx.x & 31, wid = threadIdx.x >> 5;
    if (lane == 0) sh[wid] = v;
    __syncthreads();
    v = (threadIdx.x < 8) ? sh[threadIdx.x] : 0.0f;
    if (wid == 0) {
#pragma unroll
        for (int o = 4; o > 0; o >>= 1) v += __shfl_down_sync(0xffffffffu, v, o);
    }
    return v;
}

__device__ __forceinline__ float blockReduceMax(float v) {
    __shared__ float sh[8];
#pragma unroll
    for (int o = 16; o > 0; o >>= 1) v = fmaxf(v, __shfl_down_sync(0xffffffffu, v, o));
    int lane = threadIdx.x & 31, wid = threadIdx.x >> 5;
    if (lane == 0) sh[wid] = v;
    __syncthreads();
    v = (threadIdx.x < 8) ? sh[threadIdx.x] : 0.0f;
    if (wid == 0) {
#pragma unroll
        for (int o = 4; o > 0; o >>= 1) v = fmaxf(v, __shfl_down_sync(0xffffffffu, v, o));
    }
    return v;
}

// ---------------------------------------------------------------------------
// cp-map inner value at padded coordinate q (window = 6x6 of padded values,
// base points at padded coord (q-3, q-3), row stride INSTRIDE).
// Frame row for kernel-size k element i:  i - k/2 + 3.
// ---------------------------------------------------------------------------
#define INSTRIDE 40

__device__ __forceinline__ float cp_value(const float* __restrict__ base) {
    float w[36];
#pragma unroll
    for (int r = 0; r < 6; ++r)
#pragma unroll
        for (int c = 0; c < 6; ++c) w[r * 6 + c] = base[r * INSTRIDE + c];

    float ssum = 0.0f;
    {
        constexpr unsigned long long KB[8] = {
            kbits("111001111"), kbits("111101101"), kbits("111100111"), kbits("101101111"),
            kbits("011101111"), kbits("111101011"), kbits("111101110"), kbits("110101111")};
#pragma unroll
        for (int kk = 0; kk < 8; ++kk) {
            float nc = 0.0f;
#pragma unroll
            for (int i = 0; i < 3; ++i)
#pragma unroll
                for (int j = 0; j < 3; ++j)
                    if ((KB[kk] >> (i * 3 + j)) & 1ull) nc += w[(i + 2) * 6 + (j + 2)];
            ssum += endpoint_sig(nc);
        }
    }
    {
        constexpr unsigned long long KB[8] = {
            kbits("0011000110011111"), kbits("1100100010011111"),
            kbits("1111100100010011"), kbits("1111100110001100"),
            kbits("1001100110011111"), kbits("1111000100011111"),
            kbits("1111100110011001"), kbits("1111100010001111")};
#pragma unroll
        for (int kk = 0; kk < 8; ++kk) {
            float nc = 0.0f;
#pragma unroll
            for (int i = 0; i < 4; ++i)
#pragma unroll
                for (int j = 0; j < 4; ++j)
                    if ((KB[kk] >> (i * 4 + j)) & 1ull) nc += w[(i + 1) * 6 + (j + 1)];
            ssum += endpoint_sig(nc);
        }
    }
    {
        constexpr unsigned long long KB[8] = {
            kbits("0001100001000011000111111"), kbits("1100010000100001000111111"),
            kbits("1111110001100001000011000"), kbits("1111110001000010000100011"),
            kbits("1111110000100001000011111"), kbits("1111100001000010000111111"),
            kbits("1111110001100011000110001"), kbits("1000110001100011000111111")};
#pragma unroll
        for (int kk = 0; kk < 8; ++kk) {
            float nc = 0.0f;
#pragma unroll
            for (int i = 0; i < 5; ++i)
#pragma unroll
                for (int j = 0; j < 5; ++j)
                    if ((KB[kk] >> (i * 5 + j)) & 1ull) nc += w[(i + 1) * 6 + (j + 1)];
            ssum += endpoint_sig(nc);
        }
    }
    {
        // GROUPS[3] = first 7 of the 8 k=6 kernels
        constexpr unsigned long long KB[7] = {
            kbits("000011000001000001000001100001111111"),
            kbits("110000100000100000100000100001111111"),
            kbits("111111100001100000100000100000110000"),
            kbits("111111100001000001000001000001000011"),
            kbits("111111100000100000100000100000111111"),
            kbits("111111000001000001000001000001111111"),
            kbits("111111100001100001100001100001100001")};
#pragma unroll
        for (int kk = 0; kk < 7; ++kk) {
            float nc = 0.0f;
#pragma unroll
            for (int i = 0; i < 6; ++i)
#pragma unroll
                for (int j = 0; j < 6; ++j)
                    if ((KB[kk] >> (i * 6 + j)) & 1ull) nc += w[i * 6 + j];
            ssum += endpoint_sig(nc);
        }
    }
    float epss = ssum * w[3 * 6 + 3];  // * padded[q] (interior => the data value)
    return sigm(10.0f * (epss - 0.5f));
}

// ---------------------------------------------------------------------------
// Fused get_cp + dilate + squared-diff kernel for one (pe, ge) pair.
// Tile: 32x32 outputs; cp region 34x34; padded-input region 39x39.
// comp!=0 => value = levelMax - stored (ring padding stays 1.0).
// ---------------------------------------------------------------------------
__global__ __launch_bounds__(256) void cp_pair_kernel(
    const float* __restrict__ pred, const float* __restrict__ gt,
    int selP, int selG, int lmP, int lmG, int comp) {
    __shared__ float smP[39 * INSTRIDE];
    __shared__ float smG[39 * INSTRIDE];
    __shared__ float cpP[34 * 36];
    __shared__ float cpG[34 * 36];

    const int b = blockIdx.z;
    const int ty0 = blockIdx.y * 32, tx0 = blockIdx.x * 32;
    const float* srcP = pick(selP, pred, gt) + (size_t)b * NPIX;
    const float* srcG = pick(selG, pred, gt) + (size_t)b * NPIX;

    float offP = 0.0f, offG = 0.0f, sgn = 1.0f;
    if (comp) { offP = g_lm[lmP]; offG = g_lm[lmG]; sgn = -1.0f; }

    // Load padded-coordinate tiles: 0 outside [0,513], 1 on the ring, data inside.
    for (int i = threadIdx.x; i < 39 * 39; i += 256) {
        int r = i / 39, c = i % 39;
        int qy = ty0 - 3 + r, qx = tx0 - 3 + c;
        float vP, vG;
        if (qy < 0 || qy > 513 || qx < 0 || qx > 513) {
            vP = 0.0f; vG = 0.0f;
        } else if (qy == 0 || qy == 513 || qx == 0 || qx == 513) {
            vP = 1.0f; vG = 1.0f;
        } else {
            int idx = (qy - 1) * WW + (qx - 1);
            vP = fmaf(sgn, srcP[idx], offP);
            vG = fmaf(sgn, srcG[idx], offG);
        }
        smP[r * INSTRIDE + c] = vP;
        smG[r * INSTRIDE + c] = vG;
    }
    __syncthreads();

    // cp maps (zero outside the 512x512 domain for the dilate zero-pad)
    for (int i = threadIdx.x; i < 34 * 34; i += 256) {
        int r = i / 34, c = i % 34;
        int y = ty0 - 1 + r, x = tx0 - 1 + c;
        float cP = 0.0f, cG = 0.0f;
        if (y >= 0 && y < HH && x >= 0 && x < WW) {
            cP = cp_value(&smP[r * INSTRIDE + c]);
            cG = cp_value(&smG[r * INSTRIDE + c]);
        }
        cpP[r * 36 + c] = cP;
        cpG[r * 36 + c] = cG;
    }
    __syncthreads();

    // dilate (3x3 ones, clip to [0,1]) + squared difference
    float acc = 0.0f;
    for (int i = threadIdx.x; i < 32 * 32; i += 256) {
        int r = i / 32, c = i % 32;
        float sP = 0.0f, sG = 0.0f;
#pragma unroll
        for (int dr = 0; dr < 3; ++dr)
#pragma unroll
            for (int dc = 0; dc < 3; ++dc) {
                sP += cpP[(r + dr) * 36 + (c + dc)];
                sG += cpG[(r + dr) * 36 + (c + dc)];
            }
        float d = fminf(sP, 1.0f) - fminf(sG, 1.0f);
        acc += d * d;
    }
    acc = blockReduceSum(acc);
    if (threadIdx.x == 0) atomicAdd(&g_loss, (double)acc);
}

// ---------------------------------------------------------------------------
// Erosion: cross conv + global max, then sig2 normalize.
// ---------------------------------------------------------------------------
__global__ __launch_bounds__(256) void erode_conv_kernel(
    const float* __restrict__ pred, const float* __restrict__ gt,
    int selSrc, int dstSel, int cmaxSlot) {
    int idx = blockIdx.x * blockDim.x + threadIdx.x;
    float s = 0.0f;
    if (idx < NTOT) {
        const float* src = pick(selSrc, pred, gt);
        int x = idx & (WW - 1), y = (idx >> 9) & (HH - 1);
        if (y > 0)      s += src[idx - WW];
        if (y < HH - 1) s += src[idx + WW];
        if (x > 0)      s += src[idx - 1];
        if (x < WW - 1) s += src[idx + 1];
        pick_buf(dstSel)[idx] = s;
    }
    float m = blockReduceMax(s);
    if (threadIdx.x == 0) atomicMax((int*)&g_cmax[cmaxSlot], __float_as_int(m));
}

__global__ __launch_bounds__(256) void erode_norm_kernel(int bufSel, int cmaxSlot, int lmSlot) {
    int idx = blockIdx.x * blockDim.x + threadIdx.x;
    float M = g_cmax[cmaxSlot];
    float inv = __fdividef(1.0f, M + 1e-8f);
    if (idx < NTOT) {
        float* buf = pick_buf(bufSel);
        buf[idx] = sigm(10.0f * (buf[idx] * inv - 0.7f));
    }
    if (idx == 0) g_lm[lmSlot] = sigm(10.0f * (M * inv - 0.7f));
}

__global__ __launch_bounds__(256) void max_kernel(const float* __restrict__ src, int lmSlot) {
    int idx = blockIdx.x * blockDim.x + threadIdx.x;
    float v = (idx < NTOT) ? src[idx] : 0.0f;
    float m = blockReduceMax(v);
    if (threadIdx.x == 0) atomicMax((int*)&g_lm[lmSlot], __float_as_int(m));
}

__global__ void init_kernel() {
    if (threadIdx.x == 0) {
        g_loss = 0.0;
#pragma unroll
        for (int i = 0; i < 4; ++i) g_cmax[i] = 0.0f;
#pragma unroll
        for (int i = 0; i < 6; ++i) g_lm[i] = 0.0f;
    }
}

__global__ void final_kernel(float* out) {
    out[0] = (float)(g_loss * (1.0 / (double)BATCH));
}

// ---------------------------------------------------------------------------
// Launch: pyramids -> 12 fused pair kernels -> scalar. Graph-capturable.
// ---------------------------------------------------------------------------
extern "C" void kernel_launch(void* const* d_in, const int* in_sizes, int n_in,
                              void* d_out, int out_size) {
    const float* pred = (const float*)d_in[0];
    const float* gt = (const float*)d_in[1];
    float* out = (float*)d_out;

    const int nb = NTOT / 256;

    init_kernel<<<1, 32>>>();
    max_kernel<<<nb, 256>>>(pred, 0);
    max_kernel<<<nb, 256>>>(gt, 1);

    // level 1
    erode_conv_kernel<<<nb, 256>>>(pred, gt, /*src*/0, /*dst*/0, /*cmax*/0);  // pred -> bufP1
    erode_norm_kernel<<<nb, 256>>>(0, 0, /*lm*/2);
    erode_conv_kernel<<<nb, 256>>>(pred, gt, 1, 1, 1);                        // gt -> bufG1
    erode_norm_kernel<<<nb, 256>>>(1, 1, 3);
    // level 2
    erode_conv_kernel<<<nb, 256>>>(pred, gt, 2, 2, 2);                        // bufP1 -> bufP2
    erode_norm_kernel<<<nb, 256>>>(2, 2, 4);
    erode_conv_kernel<<<nb, 256>>>(pred, gt, 3, 3, 3);                        // bufG1 -> bufG2
    erode_norm_kernel<<<nb, 256>>>(3, 3, 5);

    dim3 grid(WW / 32, HH / 32, BATCH);
    for (int lvl = 0; lvl < 3; ++lvl) {
        int selP = (lvl == 0) ? 0 : (lvl == 1 ? 2 : 4);
        int selG = (lvl == 0) ? 1 : (lvl == 1 ? 3 : 5);
        int lmP = 2 * lvl, lmG = 2 * lvl + 1;
        cp_pair_kernel<<<grid, 256>>>(pred, gt, selP, selG, lmP, lmG, 0);
        cp_pair_kernel<<<grid, 256>>>(pred, gt, selP, selG, lmP, lmG, 1);
    }

    final_kernel<<<1, 1>>>(out);
}

// round 7
// speedup vs baseline: 1.4114x; 1.4114x over previous
#include <cuda_runtime.h>
#define BATCH 8
#define HH 512
#define WW 512
#define NPIX (HH * WW)
#define NTOT (BATCH * NPIX)
typedef unsigned long long ull;

#define C10L 14.426950408889634f
#define C5L 7.213475204444817f

// ---------------- packed f32x2 helpers (non-volatile: CSE-able) ----------
__device__ __forceinline__ ull padd(ull a, ull b) {
    ull r; asm("add.rn.f32x2 %0,%1,%2;" : "=l"(r) : "l"(a), "l"(b)); return r;
}
__device__ __forceinline__ ull pmul(ull a, ull b) {
    ull r; asm("mul.rn.f32x2 %0,%1,%2;" : "=l"(r) : "l"(a), "l"(b)); return r;
}
__device__ __forceinline__ ull pfma(ull a, ull b, ull c) {
    ull r; asm("fma.rn.f32x2 %0,%1,%2,%3;" : "=l"(r) : "l"(a), "l"(b), "l"(c)); return r;
}
__device__ __forceinline__ ull pk(float x, float y) {
    ull r; asm("mov.b64 %0,{%1,%2};" : "=l"(r) : "f"(x), "f"(y)); return r;
}
__device__ __forceinline__ void unpk(ull a, float& x, float& y) {
    asm("mov.b64 {%0,%1},%2;" : "=f"(x), "=f"(y) : "l"(a));
}
__device__ __forceinline__ float fex2(float x) {
    float r; asm("ex2.approx.f32 %0,%1;" : "=f"(r) : "f"(x)); return r;
}

// ---------------- compile-time kernel parsing (host+device constexpr) ----
__host__ __device__ constexpr ull kbits(const char* s) {
    ull m = 0;
    for (int i = 0; s[i]; ++i) if (s[i] == '1') m |= (1ull << i);
    return m;
}
__host__ __device__ constexpr unsigned row_mask(ull bits, int k, int i, int off) {
    unsigned m = 0;
    for (int j = 0; j < k; ++j)
        if ((bits >> (i * k + j)) & 1ull) m |= 1u << (j + off);
    return m;
}

// ---------------- scratch ------------------------------------------------
__device__ float g_bufP1[NTOT];
__device__ float g_bufG1[NTOT];
__device__ float g_bufP2[NTOT];
__device__ float g_bufG2[NTOT];
__device__ float g_cmax[4];
__device__ float g_lm[6];
__device__ double g_loss;

__device__ __forceinline__ const float* pick(int sel, const float* pred, const float* gt) {
    switch (sel) {
        case 0: return pred;
        case 1: return gt;
        case 2: return g_bufP1;
        case 3: return g_bufG1;
        case 4: return g_bufP2;
        default: return g_bufG2;
    }
}
__device__ __forceinline__ float* pick_buf(int sel) {
    switch (sel) {
        case 0: return g_bufP1;
        case 1: return g_bufG1;
        case 2: return g_bufP2;
        default: return g_bufG2;
    }
}

// ---------------- reductions --------------------------------------------
__device__ __forceinline__ float blockReduceSum(float v) {
    __shared__ float sh[8];
#pragma unroll
    for (int o = 16; o > 0; o >>= 1) v += __shfl_down_sync(0xffffffffu, v, o);
    int lane = threadIdx.x & 31, wid = threadIdx.x >> 5;
    if (lane == 0) sh[wid] = v;
    __syncthreads();
    v = (threadIdx.x < 8) ? sh[threadIdx.x] : 0.0f;
    if (wid == 0)
#pragma unroll
        for (int o = 4; o > 0; o >>= 1) v += __shfl_down_sync(0xffffffffu, v, o);
    return v;
}
__device__ __forceinline__ void blockReduceMax2(float& a, float& b) {
    __shared__ float sha[8], shb[8];
#pragma unroll
    for (int o = 16; o > 0; o >>= 1) {
        a = fmaxf(a, __shfl_down_sync(0xffffffffu, a, o));
        b = fmaxf(b, __shfl_down_sync(0xffffffffu, b, o));
    }
    int lane = threadIdx.x & 31, wid = threadIdx.x >> 5;
    if (lane == 0) { sha[wid] = a; shb[wid] = b; }
    __syncthreads();
    a = (threadIdx.x < 8) ? sha[threadIdx.x] : 0.0f;
    b = (threadIdx.x < 8) ? shb[threadIdx.x] : 0.0f;
    if (wid == 0)
#pragma unroll
        for (int o = 4; o > 0; o >>= 1) {
            a = fmaxf(a, __shfl_down_sync(0xffffffffu, a, o));
            b = fmaxf(b, __shfl_down_sync(0xffffffffu, b, o));
        }
}

// ---------------- per-row segment sums -----------------------------------
#define INSTRIDE 40

// Pass 1 (k3+k4): window cols 1..4 of one row.
struct RS1 {
    ull w1, w2, w4, s12, s23, s34, s24, s14, s234, q4;
    __device__ __forceinline__ void init(const ull* __restrict__ p) {
        w1 = p[1]; w2 = p[2]; ull w3 = p[3]; w4 = p[4];
        s12 = padd(w1, w2); s23 = padd(w2, w3); s34 = padd(w3, w4);
        s24 = padd(w2, w4); s14 = padd(w1, w4);
        s234 = padd(s23, w4); q4 = padd(s12, s34);
    }
};
template <unsigned M> __device__ __forceinline__ ull rget1(const RS1& r) {
    if constexpr (M == 0x02u) return r.w1;
    else if constexpr (M == 0x04u) return r.w2;
    else if constexpr (M == 0x10u) return r.w4;
    else if constexpr (M == 0x06u) return r.s12;
    else if constexpr (M == 0x0Cu) return r.s23;
    else if constexpr (M == 0x18u) return r.s34;
    else if constexpr (M == 0x14u) return r.s24;
    else if constexpr (M == 0x12u) return r.s14;
    else if constexpr (M == 0x1Cu) return r.s234;
    else if constexpr (M == 0x1Eu) return r.q4;
    else { static_assert(M == 0xFFFFFFFFu, "bad mask p1"); return 0; }
}

// Pass 2 (k5+k6): window cols 0..5 of one row.
struct RS2 {
    ull w0, w1, w5, s01, s12, s45, s05, s15, f5, f6;
    __device__ __forceinline__ void init(const ull* __restrict__ p) {
        w0 = p[0]; w1 = p[1]; ull w2 = p[2], w3 = p[3], w4 = p[4]; w5 = p[5];
        s01 = padd(w0, w1); s12 = padd(w1, w2);
        ull s34 = padd(w3, w4);
        s45 = padd(w4, w5); s05 = padd(w0, w5); s15 = padd(w1, w5);
        f5 = padd(padd(s12, s34), w5); f6 = padd(f5, w0);
    }
};
template <unsigned M> __device__ __forceinline__ ull rget2(const RS2& r) {
    if constexpr (M == 0x01u) return r.w0;
    else if constexpr (M == 0x02u) return r.w1;
    else if constexpr (M == 0x20u) return r.w5;
    else if constexpr (M == 0x03u) return r.s01;
    else if constexpr (M == 0x06u) return r.s12;
    else if constexpr (M == 0x30u) return r.s45;
    else if constexpr (M == 0x21u) return r.s05;
    else if constexpr (M == 0x22u) return r.s15;
    else if constexpr (M == 0x3Eu) return r.f5;
    else if constexpr (M == 0x3Fu) return r.f6;
    else { static_assert(M == 0xFFFFFFFFu, "bad mask p2"); return 0; }
}

template <ull BITS, int K, int OFF, int R>
__device__ __forceinline__ void kacc1(ull& nc, const RS1& rs) {
    if constexpr (R >= OFF && R < OFF + K) {
        constexpr unsigned m = row_mask(BITS, K, R - OFF, OFF);
        if constexpr (m != 0) {
            ull v = rget1<m>(rs);
            if constexpr (R == OFF) nc = v; else nc = padd(nc, v);
        }
    }
}
template <ull BITS, int K, int OFF, int R>
__device__ __forceinline__ void kacc2(ull& nc, const RS2& rs) {
    if constexpr (R >= OFF && R < OFF + K) {
        constexpr unsigned m = row_mask(BITS, K, R - OFF, OFF);
        if constexpr (m != 0) {
            ull v = rget2<m>(rs);
            if constexpr (R == OFF) nc = v; else nc = padd(nc, v);
        }
    }
}

#define KER_P1(X) \
    X(0, "111001111", 3, 2) X(1, "111101101", 3, 2) X(2, "111100111", 3, 2) \
    X(3, "101101111", 3, 2) X(4, "011101111", 3, 2) X(5, "111101011", 3, 2) \
    X(6, "111101110", 3, 2) X(7, "110101111", 3, 2) \
    X(8, "0011000110011111", 4, 1) X(9, "1100100010011111", 4, 1) \
    X(10, "1111100100010011", 4, 1) X(11, "1111100110001100", 4, 1) \
    X(12, "1001100110011111", 4, 1) X(13, "1111000100011111", 4, 1) \
    X(14, "1111100110011001", 4, 1) X(15, "1111100010001111", 4, 1)

#define KER_P2(X) \
    X(0, "0001100001000011000111111", 5, 1) X(1, "1100010000100001000111111", 5, 1) \
    X(2, "1111110001100001000011000", 5, 1) X(3, "1111110001000010000100011", 5, 1) \
    X(4, "1111110000100001000011111", 5, 1) X(5, "1111100001000010000111111", 5, 1) \
    X(6, "1111110001100011000110001", 5, 1) X(7, "1000110001100011000111111", 5, 1) \
    X(8, "000011000001000001000001100001111111", 6, 0) \
    X(9, "110000100000100000100000100001111111", 6, 0) \
    X(10, "111111100001100000100000100000110000", 6, 0) \
    X(11, "111111100001000001000001000001000011", 6, 0) \
    X(12, "111111100000100000100000100000111111", 6, 0) \
    X(13, "111111000001000001000001000001111111", 6, 0) \
    X(14, "111111100001100001100001100001100001", 6, 0)

template <int R> __device__ __forceinline__ void row_acc1(ull* nc, const RS1& rs) {
#define X(I, S, K, O) kacc1<kbits(S), K, O, R>(nc[I], rs);
    KER_P1(X)
#undef X
}
template <int R> __device__ __forceinline__ void row_acc2(ull* nc, const RS2& rs) {
#define X(I, S, K, O) kacc2<kbits(S), K, O, R>(nc[I], rs);
    KER_P2(X)
#undef X
}

// ---------------- sigmoid batches ---------------------------------------
// le = sigmoid(clip(-10(nc-1),-10,10)) = 1/(1+t), t = 2^clamp(10L*nc-10L,±10L)
__device__ __forceinline__ void prep_t(ull nc, float& tP, float& tG) {
    ull y = pfma(nc, pk(C10L, C10L), pk(-C10L, -C10L));
    float fx, fy; unpk(y, fx, fy);
    tP = fex2(fminf(fmaxf(fx, -C10L), C10L));
    tG = fex2(fminf(fmaxf(fy, -C10L), C10L));
}
__device__ __forceinline__ float comb4(const float t[4]) {
    float u1 = 1.0f + t[0], u2 = 1.0f + t[1], u3 = 1.0f + t[2], u4 = 1.0f + t[3];
    float p12 = u1 * u2, p34 = u3 * u4;
    return __fdividef(fmaf(u1 + u2, p34, (u3 + u4) * p12), p12 * p34);
}
__device__ __forceinline__ float comb3(const float t[3]) {
    float u1 = 1.0f + t[0], u2 = 1.0f + t[1], u3 = 1.0f + t[2];
    float p12 = u1 * u2;
    return __fdividef(fmaf(u1 + u2, u3, p12), p12 * u3);
}
__device__ __forceinline__ void sig4(const ull* nc, float& aP, float& aG) {
    float tP[4], tG[4];
#pragma unroll
    for (int i = 0; i < 4; ++i) prep_t(nc[i], tP[i], tG[i]);
    aP += comb4(tP); aG += comb4(tG);
}
__device__ __forceinline__ void sig3(const ull* nc, float& aP, float& aG) {
    float tP[3], tG[3];
#pragma unroll
    for (int i = 0; i < 3; ++i) prep_t(nc[i], tP[i], tG[i]);
    aP += comb3(tP); aG += comb3(tG);
}

// ---------------- packed cp value ----------------------------------------
__device__ __forceinline__ ull cp_value_packed(const ull* __restrict__ base) {
    float aP = 0.0f, aG = 0.0f;
    ull center;
    {   // pass 1: k3 + k4 kernels, window rows 1..4
        ull nc[16];
        { RS1 rs; rs.init(base + 1 * INSTRIDE); row_acc1<1>(nc, rs); }
        { RS1 rs; rs.init(base + 2 * INSTRIDE); row_acc1<2>(nc, rs); }
        { RS1 rs; rs.init(base + 3 * INSTRIDE); row_acc1<3>(nc, rs); center = base[3 * INSTRIDE + 3]; }
        { RS1 rs; rs.init(base + 4 * INSTRIDE); row_acc1<4>(nc, rs); }
#pragma unroll
        for (int q = 0; q < 4; ++q) sig4(nc + 4 * q, aP, aG);
    }
    {   // pass 2: k5 + k6 kernels, window rows 0..5
        ull nc[15];
        { RS2 rs; rs.init(base + 0 * INSTRIDE); row_acc2<0>(nc, rs); }
        { RS2 rs; rs.init(base + 1 * INSTRIDE); row_acc2<1>(nc, rs); }
        { RS2 rs; rs.init(base + 2 * INSTRIDE); row_acc2<2>(nc, rs); }
        { RS2 rs; rs.init(base + 3 * INSTRIDE); row_acc2<3>(nc, rs); }
        { RS2 rs; rs.init(base + 4 * INSTRIDE); row_acc2<4>(nc, rs); }
        { RS2 rs; rs.init(base + 5 * INSTRIDE); row_acc2<5>(nc, rs); }
#pragma unroll
        for (int q = 0; q < 3; ++q) sig4(nc + 4 * q, aP, aG);
        sig3(nc + 12, aP, aG);
    }
    ull ep = pmul(pk(aP, aG), center);
    // cp = sigmoid(10(eps-0.5)) = 1/(1+2^(5L-10L*eps))
    ull y = pfma(ep, pk(-C10L, -C10L), pk(C5L, C5L));
    float fx, fy; unpk(y, fx, fy);
    float cpP = __fdividef(1.0f, 1.0f + fex2(fx));
    float cpG = __fdividef(1.0f, 1.0f + fex2(fy));
    return pk(cpP, cpG);
}

// ---------------- fused cp + dilate + sqdiff -----------------------------
__global__ __launch_bounds__(256, 2) void cp_pair_kernel(
    const float* __restrict__ pred, const float* __restrict__ gt,
    int selP, int selG, int lmP, int lmG, int comp) {
    __shared__ ull sm[39 * INSTRIDE];
    __shared__ ull cpT[34 * 36];

    const int b = blockIdx.z;
    const int ty0 = blockIdx.y * 32, tx0 = blockIdx.x * 32;
    const float* srcP = pick(selP, pred, gt) + (size_t)b * NPIX;
    const float* srcG = pick(selG, pred, gt) + (size_t)b * NPIX;

    float offP = 0.0f, offG = 0.0f, sgn = 1.0f;
    if (comp) { offP = g_lm[lmP]; offG = g_lm[lmG]; sgn = -1.0f; }

    for (int i = threadIdx.x; i < 39 * 39; i += 256) {
        int r = i / 39, c = i % 39;
        int qy = ty0 - 3 + r, qx = tx0 - 3 + c;
        float vP, vG;
        if (qy < 0 || qy > 513 || qx < 0 || qx > 513) { vP = 0.0f; vG = 0.0f; }
        else if (qy == 0 || qy == 513 || qx == 0 || qx == 513) { vP = 1.0f; vG = 1.0f; }
        else {
            int idx = (qy - 1) * WW + (qx - 1);
            vP = fmaf(sgn, srcP[idx], offP);
            vG = fmaf(sgn, srcG[idx], offG);
        }
        sm[r * INSTRIDE + c] = pk(vP, vG);
    }
    __syncthreads();

    for (int i = threadIdx.x; i < 34 * 34; i += 256) {
        int r = i / 34, c = i % 34;
        int y = ty0 - 1 + r, x = tx0 - 1 + c;
        ull v = 0ull;
        if (y >= 0 && y < HH && x >= 0 && x < WW)
            v = cp_value_packed(&sm[r * INSTRIDE + c]);
        cpT[r * 36 + c] = v;
    }
    __syncthreads();

    float acc = 0.0f;
    for (int i = threadIdx.x; i < 32 * 32; i += 256) {
        int r = i / 32, c = i % 32;
        ull s = cpT[r * 36 + c];
        s = padd(s, cpT[r * 36 + c + 1]);
        s = padd(s, cpT[r * 36 + c + 2]);
        s = padd(s, cpT[(r + 1) * 36 + c]);
        s = padd(s, cpT[(r + 1) * 36 + c + 1]);
        s = padd(s, cpT[(r + 1) * 36 + c + 2]);
        s = padd(s, cpT[(r + 2) * 36 + c]);
        s = padd(s, cpT[(r + 2) * 36 + c + 1]);
        s = padd(s, cpT[(r + 2) * 36 + c + 2]);
        float sP, sG; unpk(s, sP, sG);
        float d = fminf(sP, 1.0f) - fminf(sG, 1.0f);
        acc = fmaf(d, d, acc);
    }
    acc = blockReduceSum(acc);
    if (threadIdx.x == 0) atomicAdd(&g_loss, (double)acc);
}

// ---------------- fused erosion (P and G, 4 px/thread) -------------------
__global__ __launch_bounds__(256) void erode_conv2_kernel(
    const float* __restrict__ pred, const float* __restrict__ gt,
    int selP, int selG, int dstP, int dstG, int slotP, int slotG) {
    int t = blockIdx.x * 256 + threadIdx.x;
    int pix = t * 4;
    int y = (pix >> 9) & (HH - 1);
    int x = pix & (WW - 1);
    const float* sP = pick(selP, pred, gt);
    const float* sG = pick(selG, pred, gt);

    float4 cP = *(const float4*)(sP + pix);
    float4 cG = *(const float4*)(sG + pix);
    float4 uP = make_float4(0, 0, 0, 0), uG = uP, dP = uP, dG = uP;
    if (y > 0)      { uP = *(const float4*)(sP + pix - WW); uG = *(const float4*)(sG + pix - WW); }
    if (y < HH - 1) { dP = *(const float4*)(sP + pix + WW); dG = *(const float4*)(sG + pix + WW); }
    float lP = (x > 0) ? sP[pix - 1] : 0.0f;
    float lG = (x > 0) ? sG[pix - 1] : 0.0f;
    float rP = (x < WW - 4) ? sP[pix + 4] : 0.0f;
    float rG = (x < WW - 4) ? sG[pix + 4] : 0.0f;

    float4 oP, oG;
    oP.x = lP + cP.y + uP.x + dP.x;
    oP.y = cP.x + cP.z + uP.y + dP.y;
    oP.z = cP.y + cP.w + uP.z + dP.z;
    oP.w = cP.z + rP + uP.w + dP.w;
    oG.x = lG + cG.y + uG.x + dG.x;
    oG.y = cG.x + cG.z + uG.y + dG.y;
    oG.z = cG.y + cG.w + uG.z + dG.z;
    oG.w = cG.z + rG + uG.w + dG.w;

    *(float4*)(pick_buf(dstP) + pix) = oP;
    *(float4*)(pick_buf(dstG) + pix) = oG;

    float mP = fmaxf(fmaxf(oP.x, oP.y), fmaxf(oP.z, oP.w));
    float mG = fmaxf(fmaxf(oG.x, oG.y), fmaxf(oG.z, oG.w));
    blockReduceMax2(mP, mG);
    if (threadIdx.x == 0) {
        atomicMax((int*)&g_cmax[slotP], __float_as_int(mP));
        atomicMax((int*)&g_cmax[slotG], __float_as_int(mG));
    }
}

__global__ __launch_bounds__(256) void erode_norm2_kernel(
    int bufP, int bufG, int slotP, int slotG, int lmP, int lmG) {
    int t = blockIdx.x * 256 + threadIdx.x;
    int pix = t * 4;
    const float C7L = 0.7f * C10L;
    float MP = g_cmax[slotP], MG = g_cmax[slotG];
    float kP = -C10L * __fdividef(1.0f, MP + 1e-8f);
    float kG = -C10L * __fdividef(1.0f, MG + 1e-8f);

    float4* bP = (float4*)(pick_buf(bufP) + pix);
    float4* bG = (float4*)(pick_buf(bufG) + pix);
    float4 vP = *bP, vG = *bG;
    vP.x = __fdividef(1.0f, 1.0f + fex2(fmaf(vP.x, kP, C7L)));
    vP.y = __fdividef(1.0f, 1.0f + fex2(fmaf(vP.y, kP, C7L)));
    vP.z = __fdividef(1.0f, 1.0f + fex2(fmaf(vP.z, kP, C7L)));
    vP.w = __fdividef(1.0f, 1.0f + fex2(fmaf(vP.w, kP, C7L)));
    vG.x = __fdividef(1.0f, 1.0f + fex2(fmaf(vG.x, kG, C7L)));
    vG.y = __fdividef(1.0f, 1.0f + fex2(fmaf(vG.y, kG, C7L)));
    vG.z = __fdividef(1.0f, 1.0f + fex2(fmaf(vG.z, kG, C7L)));
    vG.w = __fdividef(1.0f, 1.0f + fex2(fmaf(vG.w, kG, C7L)));
    *bP = vP;
    *bG = vG;

    if (blockIdx.x == 0 && threadIdx.x == 0) {
        g_lm[lmP] = __fdividef(1.0f, 1.0f + fex2(fmaf(MP, kP, C7L)));
        g_lm[lmG] = __fdividef(1.0f, 1.0f + fex2(fmaf(MG, kG, C7L)));
    }
}

__global__ __launch_bounds__(256) void maxPG_kernel(
    const float* __restrict__ pred, const float* __restrict__ gt) {
    int t = blockIdx.x * 256 + threadIdx.x;
    float4 a = ((const float4*)pred)[t];
    float4 b = ((const float4*)gt)[t];
    float mP = fmaxf(fmaxf(a.x, a.y), fmaxf(a.z, a.w));
    float mG = fmaxf(fmaxf(b.x, b.y), fmaxf(b.z, b.w));
    blockReduceMax2(mP, mG);
    if (threadIdx.x == 0) {
        atomicMax((int*)&g_lm[0], __float_as_int(mP));
        atomicMax((int*)&g_lm[1], __float_as_int(mG));
    }
}

__global__ void init_kernel() {
    if (threadIdx.x == 0) {
        g_loss = 0.0;
#pragma unroll
        for (int i = 0; i < 4; ++i) g_cmax[i] = 0.0f;
#pragma unroll
        for (int i = 0; i < 6; ++i) g_lm[i] = 0.0f;
    }
}
__global__ void final_kernel(float* out) {
    out[0] = (float)(g_loss * (1.0 / (double)BATCH));
}

// ---------------- launch --------------------------------------------------
extern "C" void kernel_launch(void* const* d_in, const int* in_sizes, int n_in,
                              void* d_out, int out_size) {
    const float* pred = (const float*)d_in[0];
    const float* gt = (const float*)d_in[1];
    float* out = (float*)d_out;
    const int nb4 = NTOT / 1024;

    init_kernel<<<1, 32>>>();
    maxPG_kernel<<<nb4, 256>>>(pred, gt);

    erode_conv2_kernel<<<nb4, 256>>>(pred, gt, 0, 1, 0, 1, 0, 1);  // lvl0 -> P1,G1
    erode_norm2_kernel<<<nb4, 256>>>(0, 1, 0, 1, 2, 3);
    erode_conv2_kernel<<<nb4, 256>>>(pred, gt, 2, 3, 2, 3, 2, 3);  // lvl1 -> P2,G2
    erode_norm2_kernel<<<nb4, 256>>>(2, 3, 2, 3, 4, 5);

    dim3 grid(WW / 32, HH / 32, BATCH);
    for (int lvl = 0; lvl < 3; ++lvl) {
        int selP = (lvl == 0) ? 0 : (lvl == 1 ? 2 : 4);
        int selG = (lvl == 0) ? 1 : (lvl == 1 ? 3 : 5);
        cp_pair_kernel<<<grid, 256>>>(pred, gt, selP, selG, 2 * lvl, 2 * lvl + 1, 0);
        cp_pair_kernel<<<grid, 256>>>(pred, gt, selP, selG, 2 * lvl, 2 * lvl + 1, 1);
    }

    final_kernel<<<1, 1>>>(out);
}

// round 8
// speedup vs baseline: 1.6315x; 1.1559x over previous
#include <cuda_runtime.h>
#define BATCH 8
#define HH 512
#define WW 512
#define NPIX (HH * WW)
#define NTOT (BATCH * NPIX)
typedef unsigned long long ull;

#define C10L 14.426950408889634f
#define C5L 7.213475204444817f

// ---------------- packed f32x2 helpers (non-volatile: CSE-able) ----------
__device__ __forceinline__ ull padd(ull a, ull b) {
    ull r; asm("add.rn.f32x2 %0,%1,%2;" : "=l"(r) : "l"(a), "l"(b)); return r;
}
__device__ __forceinline__ ull pmul(ull a, ull b) {
    ull r; asm("mul.rn.f32x2 %0,%1,%2;" : "=l"(r) : "l"(a), "l"(b)); return r;
}
__device__ __forceinline__ ull pfma(ull a, ull b, ull c) {
    ull r; asm("fma.rn.f32x2 %0,%1,%2,%3;" : "=l"(r) : "l"(a), "l"(b), "l"(c)); return r;
}
__device__ __forceinline__ ull pk(float x, float y) {
    ull r; asm("mov.b64 %0,{%1,%2};" : "=l"(r) : "f"(x), "f"(y)); return r;
}
__device__ __forceinline__ void unpk(ull a, float& x, float& y) {
    asm("mov.b64 {%0,%1},%2;" : "=f"(x), "=f"(y) : "l"(a));
}
__device__ __forceinline__ float fex2(float x) {
    float r; asm("ex2.approx.f32 %0,%1;" : "=f"(r) : "f"(x)); return r;
}

// ---------------- compile-time kernel parsing (host+device constexpr) ----
__host__ __device__ constexpr ull kbits(const char* s) {
    ull m = 0;
    for (int i = 0; s[i]; ++i) if (s[i] == '1') m |= (1ull << i);
    return m;
}
__host__ __device__ constexpr unsigned row_mask(ull bits, int k, int i, int off) {
    unsigned m = 0;
    for (int j = 0; j < k; ++j)
        if ((bits >> (i * k + j)) & 1ull) m |= 1u << (j + off);
    return m;
}
__host__ __device__ constexpr float kcntf(const char* s) {
    int c = 0;
    for (int i = 0; s[i]; ++i) if (s[i] == '1') ++c;
    return (float)c;
}

// ---------------- scratch ------------------------------------------------
__device__ float g_bufP1[NTOT];
__device__ float g_bufG1[NTOT];
__device__ float g_bufP2[NTOT];
__device__ float g_bufG2[NTOT];
__device__ float g_cmax[4];
__device__ float g_lm[6];
__device__ double g_loss;

__device__ __forceinline__ const float* pick(int sel, const float* pred, const float* gt) {
    switch (sel) {
        case 0: return pred;
        case 1: return gt;
        case 2: return g_bufP1;
        case 3: return g_bufG1;
        case 4: return g_bufP2;
        default: return g_bufG2;
    }
}
__device__ __forceinline__ float* pick_buf(int sel) {
    switch (sel) {
        case 0: return g_bufP1;
        case 1: return g_bufG1;
        case 2: return g_bufP2;
        default: return g_bufG2;
    }
}

// ---------------- reductions --------------------------------------------
__device__ __forceinline__ float blockReduceSum(float v) {
    __shared__ float sh[8];
#pragma unroll
    for (int o = 16; o > 0; o >>= 1) v += __shfl_down_sync(0xffffffffu, v, o);
    int lane = threadIdx.x & 31, wid = threadIdx.x >> 5;
    if (lane == 0) sh[wid] = v;
    __syncthreads();
    v = (threadIdx.x < 8) ? sh[threadIdx.x] : 0.0f;
    if (wid == 0)
#pragma unroll
        for (int o = 4; o > 0; o >>= 1) v += __shfl_down_sync(0xffffffffu, v, o);
    return v;
}
__device__ __forceinline__ void blockReduceMax2(float& a, float& b) {
    __shared__ float sha[8], shb[8];
#pragma unroll
    for (int o = 16; o > 0; o >>= 1) {
        a = fmaxf(a, __shfl_down_sync(0xffffffffu, a, o));
        b = fmaxf(b, __shfl_down_sync(0xffffffffu, b, o));
    }
    int lane = threadIdx.x & 31, wid = threadIdx.x >> 5;
    if (lane == 0) { sha[wid] = a; shb[wid] = b; }
    __syncthreads();
    a = (threadIdx.x < 8) ? sha[threadIdx.x] : 0.0f;
    b = (threadIdx.x < 8) ? shb[threadIdx.x] : 0.0f;
    if (wid == 0)
#pragma unroll
        for (int o = 4; o > 0; o >>= 1) {
            a = fmaxf(a, __shfl_down_sync(0xffffffffu, a, o));
            b = fmaxf(b, __shfl_down_sync(0xffffffffu, b, o));
        }
}

// ---------------- per-row segment sums -----------------------------------
#define INSTRIDE 40

// Pass 1 (k3+k4): window cols 1..4 of one row.
struct RS1 {
    ull w1, w2, w4, s12, s23, s34, s24, s14, s234, q4;
    __device__ __forceinline__ void init(const ull* __restrict__ p) {
        w1 = p[1]; w2 = p[2]; ull w3 = p[3]; w4 = p[4];
        s12 = padd(w1, w2); s23 = padd(w2, w3); s34 = padd(w3, w4);
        s24 = padd(w2, w4); s14 = padd(w1, w4);
        s234 = padd(s23, w4); q4 = padd(s12, s34);
    }
};
template <unsigned M> __device__ __forceinline__ ull rget1(const RS1& r) {
    if constexpr (M == 0x02u) return r.w1;
    else if constexpr (M == 0x04u) return r.w2;
    else if constexpr (M == 0x10u) return r.w4;
    else if constexpr (M == 0x06u) return r.s12;
    else if constexpr (M == 0x0Cu) return r.s23;
    else if constexpr (M == 0x18u) return r.s34;
    else if constexpr (M == 0x14u) return r.s24;
    else if constexpr (M == 0x12u) return r.s14;
    else if constexpr (M == 0x1Cu) return r.s234;
    else if constexpr (M == 0x1Eu) return r.q4;
    else { static_assert(M == 0xFFFFFFFFu, "bad mask p1"); return 0; }
}

// Pass 2 (k5+k6): window cols 0..5 of one row.
struct RS2 {
    ull w0, w1, w5, s01, s12, s45, s05, s15, f5, f6;
    __device__ __forceinline__ void init(const ull* __restrict__ p) {
        w0 = p[0]; w1 = p[1]; ull w2 = p[2], w3 = p[3], w4 = p[4]; w5 = p[5];
        s01 = padd(w0, w1); s12 = padd(w1, w2);
        ull s34 = padd(w3, w4);
        s45 = padd(w4, w5); s05 = padd(w0, w5); s15 = padd(w1, w5);
        f5 = padd(padd(s12, s34), w5); f6 = padd(f5, w0);
    }
};
template <unsigned M> __device__ __forceinline__ ull rget2(const RS2& r) {
    if constexpr (M == 0x01u) return r.w0;
    else if constexpr (M == 0x02u) return r.w1;
    else if constexpr (M == 0x20u) return r.w5;
    else if constexpr (M == 0x03u) return r.s01;
    else if constexpr (M == 0x06u) return r.s12;
    else if constexpr (M == 0x30u) return r.s45;
    else if constexpr (M == 0x21u) return r.s05;
    else if constexpr (M == 0x22u) return r.s15;
    else if constexpr (M == 0x3Eu) return r.f5;
    else if constexpr (M == 0x3Fu) return r.f6;
    else { static_assert(M == 0xFFFFFFFFu, "bad mask p2"); return 0; }
}

template <ull BITS, int K, int OFF, int R>
__device__ __forceinline__ void kacc1(ull& nc, const RS1& rs) {
    if constexpr (R >= OFF && R < OFF + K) {
        constexpr unsigned m = row_mask(BITS, K, R - OFF, OFF);
        if constexpr (m != 0) {
            ull v = rget1<m>(rs);
            if constexpr (R == OFF) nc = v; else nc = padd(nc, v);
        }
    }
}
template <ull BITS, int K, int OFF, int R>
__device__ __forceinline__ void kacc2(ull& nc, const RS2& rs) {
    if constexpr (R >= OFF && R < OFF + K) {
        constexpr unsigned m = row_mask(BITS, K, R - OFF, OFF);
        if constexpr (m != 0) {
            ull v = rget2<m>(rs);
            if constexpr (R == OFF) nc = v; else nc = padd(nc, v);
        }
    }
}

#define KER_P1(X) \
    X(0, "111001111", 3, 2) X(1, "111101101", 3, 2) X(2, "111100111", 3, 2) \
    X(3, "101101111", 3, 2) X(4, "011101111", 3, 2) X(5, "111101011", 3, 2) \
    X(6, "111101110", 3, 2) X(7, "110101111", 3, 2) \
    X(8, "0011000110011111", 4, 1) X(9, "1100100010011111", 4, 1) \
    X(10, "1111100100010011", 4, 1) X(11, "1111100110001100", 4, 1) \
    X(12, "1001100110011111", 4, 1) X(13, "1111000100011111", 4, 1) \
    X(14, "1111100110011001", 4, 1) X(15, "1111100010001111", 4, 1)

#define KER_P2(X) \
    X(0, "0001100001000011000111111", 5, 1) X(1, "1100010000100001000111111", 5, 1) \
    X(2, "1111110001100001000011000", 5, 1) X(3, "1111110001000010000100011", 5, 1) \
    X(4, "1111110000100001000011111", 5, 1) X(5, "1111100001000010000111111", 5, 1) \
    X(6, "1111110001100011000110001", 5, 1) X(7, "1000110001100011000111111", 5, 1) \
    X(8, "000011000001000001000001100001111111", 6, 0) \
    X(9, "110000100000100000100000100001111111", 6, 0) \
    X(10, "111111100001100000100000100000110000", 6, 0) \
    X(11, "111111100001000001000001000001000011", 6, 0) \
    X(12, "111111100000100000100000100000111111", 6, 0) \
    X(13, "111111000001000001000001000001111111", 6, 0) \
    X(14, "111111100001100001100001100001100001", 6, 0)

template <int R> __device__ __forceinline__ void row_acc1(ull* nc, const RS1& rs) {
#define X(I, S, K, O) kacc1<kbits(S), K, O, R>(nc[I], rs);
    KER_P1(X)
#undef X
}
template <int R> __device__ __forceinline__ void row_acc2(ull* nc, const RS2& rs) {
#define X(I, S, K, O) kacc2<kbits(S), K, O, R>(nc[I], rs);
    KER_P2(X)
#undef X
}

// Popcount of each kernel (compile-time foldable accessors).
__host__ __device__ constexpr float cntp1(int i) {
#define X(I, S, K, O) if (i == I) return kcntf(S);
    KER_P1(X)
#undef X
    return 0.0f;
}
__host__ __device__ constexpr float cntp2(int i) {
#define X(I, S, K, O) if (i == I) return kcntf(S);
    KER_P2(X)
#undef X
    return 0.0f;
}

// ---------------- sigmoid batches ---------------------------------------
// le = sigmoid(clip(-10(nc-1),-10,10)) = 1/(1+t), t = 2^min(10L*nc-10L, 10L)
// (lower clamp never binds: all window values >= 0 => nc >= 0 => arg >= -10L)
__device__ __forceinline__ void prep_t(ull nc, float& tP, float& tG) {
    ull y = pfma(nc, pk(C10L, C10L), pk(-C10L, -C10L));
    float fx, fy; unpk(y, fx, fy);
    tP = fex2(fminf(fx, C10L));
    tG = fex2(fminf(fy, C10L));
}
// dual: direct + complement via linearity: nc_c = cnt*lm - nc (interior only)
// y_c = 10L*nc_c - 10L = cnt*(10L*lm) - 10L - 10L*nc
__device__ __forceinline__ void prep_dual(ull nc, float cnt, ull lm10,
                                          float& tPd, float& tGd, float& tPc, float& tGc) {
    const ull N10 = pk(-C10L, -C10L);
    ull yd = pfma(nc, pk(C10L, C10L), N10);
    float fx, fy; unpk(yd, fx, fy);
    tPd = fex2(fminf(fx, C10L));
    tGd = fex2(fminf(fy, C10L));
    ull ck = pfma(pk(cnt, cnt), lm10, N10);
    ull yc = pfma(nc, N10, ck);
    unpk(yc, fx, fy);
    tPc = fex2(fminf(fx, C10L));
    tGc = fex2(fminf(fy, C10L));
}
__device__ __forceinline__ float comb4(const float t[4]) {
    float u1 = 1.0f + t[0], u2 = 1.0f + t[1], u3 = 1.0f + t[2], u4 = 1.0f + t[3];
    float p12 = u1 * u2, p34 = u3 * u4;
    return __fdividef(fmaf(u1 + u2, p34, (u3 + u4) * p12), p12 * p34);
}
__device__ __forceinline__ float comb3(const float t[3]) {
    float u1 = 1.0f + t[0], u2 = 1.0f + t[1], u3 = 1.0f + t[2];
    float p12 = u1 * u2;
    return __fdividef(fmaf(u1 + u2, u3, p12), p12 * u3);
}
__device__ __forceinline__ void sig4(const ull* nc, float& aP, float& aG) {
    float tP[4], tG[4];
#pragma unroll
    for (int i = 0; i < 4; ++i) prep_t(nc[i], tP[i], tG[i]);
    aP += comb4(tP); aG += comb4(tG);
}
__device__ __forceinline__ void sig3(const ull* nc, float& aP, float& aG) {
    float tP[3], tG[3];
#pragma unroll
    for (int i = 0; i < 3; ++i) prep_t(nc[i], tP[i], tG[i]);
    aP += comb3(tP); aG += comb3(tG);
}
__device__ __forceinline__ void sig4_dual(const ull* nc, int b, int pass1, ull lm10,
                                          float& aPd, float& aGd, float& aPc, float& aGc) {
    float tPd[4], tGd[4], tPc[4], tGc[4];
#pragma unroll
    for (int i = 0; i < 4; ++i) {
        float cnt = pass1 ? cntp1(b + i) : cntp2(b + i);
        prep_dual(nc[i], cnt, lm10, tPd[i], tGd[i], tPc[i], tGc[i]);
    }
    aPd += comb4(tPd); aGd += comb4(tGd);
    aPc += comb4(tPc); aGc += comb4(tGc);
}
__device__ __forceinline__ void sig3_dual(const ull* nc, int b, ull lm10,
                                          float& aPd, float& aGd, float& aPc, float& aGc) {
    float tPd[3], tGd[3], tPc[3], tGc[3];
#pragma unroll
    for (int i = 0; i < 3; ++i)
        prep_dual(nc[i], cntp2(b + i), lm10, tPd[i], tGd[i], tPc[i], tGc[i]);
    aPd += comb3(tPd); aGd += comb3(tGd);
    aPc += comb3(tPc); aGc += comb3(tGc);
}

// ---------------- packed cp value (single variant, slow path) ------------
__device__ __forceinline__ ull cp_value_packed(const ull* __restrict__ base) {
    float aP = 0.0f, aG = 0.0f;
    ull center;
    {   // pass 1: k3 + k4 kernels, window rows 1..4
        ull nc[16];
        { RS1 rs; rs.init(base + 1 * INSTRIDE); row_acc1<1>(nc, rs); }
        { RS1 rs; rs.init(base + 2 * INSTRIDE); row_acc1<2>(nc, rs); }
        { RS1 rs; rs.init(base + 3 * INSTRIDE); row_acc1<3>(nc, rs); center = base[3 * INSTRIDE + 3]; }
        { RS1 rs; rs.init(base + 4 * INSTRIDE); row_acc1<4>(nc, rs); }
#pragma unroll
        for (int q = 0; q < 4; ++q) sig4(nc + 4 * q, aP, aG);
    }
    {   // pass 2: k5 + k6 kernels, window rows 0..5
        ull nc[15];
        { RS2 rs; rs.init(base + 0 * INSTRIDE); row_acc2<0>(nc, rs); }
        { RS2 rs; rs.init(base + 1 * INSTRIDE); row_acc2<1>(nc, rs); }
        { RS2 rs; rs.init(base + 2 * INSTRIDE); row_acc2<2>(nc, rs); }
        { RS2 rs; rs.init(base + 3 * INSTRIDE); row_acc2<3>(nc, rs); }
        { RS2 rs; rs.init(base + 4 * INSTRIDE); row_acc2<4>(nc, rs); }
        { RS2 rs; rs.init(base + 5 * INSTRIDE); row_acc2<5>(nc, rs); }
#pragma unroll
        for (int q = 0; q < 3; ++q) sig4(nc + 4 * q, aP, aG);
        sig3(nc + 12, aP, aG);
    }
    ull ep = pmul(pk(aP, aG), center);
    ull y = pfma(ep, pk(-C10L, -C10L), pk(C5L, C5L));
    float fx, fy; unpk(y, fx, fy);
    float cpP = __fdividef(1.0f, 1.0f + fex2(fx));
    float cpG = __fdividef(1.0f, 1.0f + fex2(fy));
    return pk(cpP, cpG);
}

// ---------------- dual cp value (interior: comp via linearity) -----------
__device__ __forceinline__ void cp_value_dual(const ull* __restrict__ base,
                                              ull lm_pk, ull lm10,
                                              ull& cpd, ull& cpc) {
    float aPd = 0.0f, aGd = 0.0f, aPc = 0.0f, aGc = 0.0f;
    ull center;
    {   // pass 1
        ull nc[16];
        { RS1 rs; rs.init(base + 1 * INSTRIDE); row_acc1<1>(nc, rs); }
        { RS1 rs; rs.init(base + 2 * INSTRIDE); row_acc1<2>(nc, rs); }
        { RS1 rs; rs.init(base + 3 * INSTRIDE); row_acc1<3>(nc, rs); center = base[3 * INSTRIDE + 3]; }
        { RS1 rs; rs.init(base + 4 * INSTRIDE); row_acc1<4>(nc, rs); }
#pragma unroll
        for (int q = 0; q < 4; ++q) sig4_dual(nc + 4 * q, 4 * q, 1, lm10, aPd, aGd, aPc, aGc);
    }
    {   // pass 2
        ull nc[15];
        { RS2 rs; rs.init(base + 0 * INSTRIDE); row_acc2<0>(nc, rs); }
        { RS2 rs; rs.init(base + 1 * INSTRIDE); row_acc2<1>(nc, rs); }
        { RS2 rs; rs.init(base + 2 * INSTRIDE); row_acc2<2>(nc, rs); }
        { RS2 rs; rs.init(base + 3 * INSTRIDE); row_acc2<3>(nc, rs); }
        { RS2 rs; rs.init(base + 4 * INSTRIDE); row_acc2<4>(nc, rs); }
        { RS2 rs; rs.init(base + 5 * INSTRIDE); row_acc2<5>(nc, rs); }
#pragma unroll
        for (int q = 0; q < 3; ++q) sig4_dual(nc + 4 * q, 4 * q, 0, lm10, aPd, aGd, aPc, aGc);
        sig3_dual(nc + 12, 12, lm10, aPd, aGd, aPc, aGc);
    }
    // center_c = lm - center
    ull center_c = pfma(center, pk(-1.0f, -1.0f), lm_pk);
    ull epd = pmul(pk(aPd, aGd), center);
    ull epc = pmul(pk(aPc, aGc), center_c);
    const ull N10 = pk(-C10L, -C10L), P5 = pk(C5L, C5L);
    ull yd = pfma(epd, N10, P5);
    ull yc = pfma(epc, N10, P5);
    float fx, fy;
    unpk(yd, fx, fy);
    cpd = pk(__fdividef(1.0f, 1.0f + fex2(fx)), __fdividef(1.0f, 1.0f + fex2(fy)));
    unpk(yc, fx, fy);
    cpc = pk(__fdividef(1.0f, 1.0f + fex2(fx)), __fdividef(1.0f, 1.0f + fex2(fy)));
}

// ---------------- fused dual (direct+complement) cp kernel ----------------
// One launch per pyramid level: computes sum of squared diffs for BOTH the
// direct and complement get_cp maps of (pe, ge).
__global__ __launch_bounds__(256, 2) void cp_dual_kernel(
    const float* __restrict__ pred, const float* __restrict__ gt,
    int selP, int selG, int lmP, int lmG) {
    __shared__ ull sm[39 * INSTRIDE];
    __shared__ ull smC[39 * INSTRIDE];
    __shared__ ull cpD[34 * 36];
    __shared__ ull cpC[34 * 36];

    const int b = blockIdx.z;
    const int ty0 = blockIdx.y * 32, tx0 = blockIdx.x * 32;
    const float* srcP = pick(selP, pred, gt) + (size_t)b * NPIX;
    const float* srcG = pick(selG, pred, gt) + (size_t)b * NPIX;

    const float lmPv = g_lm[lmP], lmGv = g_lm[lmG];
    const ull lm_pk = pk(lmPv, lmGv);
    const ull lm10 = pmul(lm_pk, pk(C10L, C10L));
    // interior: every window used by this block stays inside padded [1,512]²
    const bool interior = (blockIdx.x >= 1 && blockIdx.x <= 14 &&
                           blockIdx.y >= 1 && blockIdx.y <= 14);

    for (int i = threadIdx.x; i < 39 * 39; i += 256) {
        int r = i / 39, c = i % 39;
        int qy = ty0 - 3 + r, qx = tx0 - 3 + c;
        float vP, vG, wP, wG;
        if (qy < 0 || qy > 513 || qx < 0 || qx > 513) {
            vP = 0.0f; vG = 0.0f; wP = 0.0f; wG = 0.0f;
        } else if (qy == 0 || qy == 513 || qx == 0 || qx == 513) {
            vP = 1.0f; vG = 1.0f; wP = 1.0f; wG = 1.0f;
        } else {
            int idx = (qy - 1) * WW + (qx - 1);
            vP = srcP[idx]; vG = srcG[idx];
            wP = lmPv - vP; wG = lmGv - vG;
        }
        sm[r * INSTRIDE + c] = pk(vP, vG);
        if (!interior) smC[r * INSTRIDE + c] = pk(wP, wG);
    }
    __syncthreads();

    for (int i = threadIdx.x; i < 34 * 34; i += 256) {
        int r = i / 34, c = i % 34;
        int y = ty0 - 1 + r, x = tx0 - 1 + c;
        ull vd = 0ull, vc = 0ull;
        if (y >= 0 && y < HH && x >= 0 && x < WW) {
            if (interior) {
                cp_value_dual(&sm[r * INSTRIDE + c], lm_pk, lm10, vd, vc);
            } else {
                vd = cp_value_packed(&sm[r * INSTRIDE + c]);
                vc = cp_value_packed(&smC[r * INSTRIDE + c]);
            }
        }
        cpD[r * 36 + c] = vd;
        cpC[r * 36 + c] = vc;
    }
    __syncthreads();

    float acc = 0.0f;
    for (int i = threadIdx.x; i < 32 * 32; i += 256) {
        int r = i / 32, c = i % 32;
        ull sd = cpD[r * 36 + c], sc = cpC[r * 36 + c];
#pragma unroll
        for (int dr = 0; dr < 3; ++dr)
#pragma unroll
            for (int dc = 0; dc < 3; ++dc) {
                if (dr == 0 && dc == 0) continue;
                sd = padd(sd, cpD[(r + dr) * 36 + (c + dc)]);
                sc = padd(sc, cpC[(r + dr) * 36 + (c + dc)]);
            }
        float sP, sG, tP, tG;
        unpk(sd, sP, sG);
        unpk(sc, tP, tG);
        float d1 = fminf(sP, 1.0f) - fminf(sG, 1.0f);
        float d2 = fminf(tP, 1.0f) - fminf(tG, 1.0f);
        acc = fmaf(d1, d1, acc);
        acc = fmaf(d2, d2, acc);
    }
    acc = blockReduceSum(acc);
    if (threadIdx.x == 0) atomicAdd(&g_loss, (double)acc);
}

// ---------------- fused erosion (P and G, 4 px/thread) -------------------
__global__ __launch_bounds__(256) void erode_conv2_kernel(
    const float* __restrict__ pred, const float* __restrict__ gt,
    int selP, int selG, int dstP, int dstG, int slotP, int slotG) {
    int t = blockIdx.x * 256 + threadIdx.x;
    int pix = t * 4;
    int y = (pix >> 9) & (HH - 1);
    int x = pix & (WW - 1);
    const float* sP = pick(selP, pred, gt);
    const float* sG = pick(selG, pred, gt);

    float4 cP = *(const float4*)(sP + pix);
    float4 cG = *(const float4*)(sG + pix);
    float4 uP = make_float4(0, 0, 0, 0), uG = uP, dP = uP, dG = uP;
    if (y > 0)      { uP = *(const float4*)(sP + pix - WW); uG = *(const float4*)(sG + pix - WW); }
    if (y < HH - 1) { dP = *(const float4*)(sP + pix + WW); dG = *(const float4*)(sG + pix + WW); }
    float lP = (x > 0) ? sP[pix - 1] : 0.0f;
    float lG = (x > 0) ? sG[pix - 1] : 0.0f;
    float rP = (x < WW - 4) ? sP[pix + 4] : 0.0f;
    float rG = (x < WW - 4) ? sG[pix + 4] : 0.0f;

    float4 oP, oG;
    oP.x = lP + cP.y + uP.x + dP.x;
    oP.y = cP.x + cP.z + uP.y + dP.y;
    oP.z = cP.y + cP.w + uP.z + dP.z;
    oP.w = cP.z + rP + uP.w + dP.w;
    oG.x = lG + cG.y + uG.x + dG.x;
    oG.y = cG.x + cG.z + uG.y + dG.y;
    oG.z = cG.y + cG.w + uG.z + dG.z;
    oG.w = cG.z + rG + uG.w + dG.w;

    *(float4*)(pick_buf(dstP) + pix) = oP;
    *(float4*)(pick_buf(dstG) + pix) = oG;

    float mP = fmaxf(fmaxf(oP.x, oP.y), fmaxf(oP.z, oP.w));
    float mG = fmaxf(fmaxf(oG.x, oG.y), fmaxf(oG.z, oG.w));
    blockReduceMax2(mP, mG);
    if (threadIdx.x == 0) {
        atomicMax((int*)&g_cmax[slotP], __float_as_int(mP));
        atomicMax((int*)&g_cmax[slotG], __float_as_int(mG));
    }
}

__global__ __launch_bounds__(256) void erode_norm2_kernel(
    int bufP, int bufG, int slotP, int slotG, int lmP, int lmG) {
    int t = blockIdx.x * 256 + threadIdx.x;
    int pix = t * 4;
    const float C7L = 0.7f * C10L;
    float MP = g_cmax[slotP], MG = g_cmax[slotG];
    float kP = -C10L * __fdividef(1.0f, MP + 1e-8f);
    float kG = -C10L * __fdividef(1.0f, MG + 1e-8f);

    float4* bP = (float4*)(pick_buf(bufP) + pix);
    float4* bG = (float4*)(pick_buf(bufG) + pix);
    float4 vP = *bP, vG = *bG;
    vP.x = __fdividef(1.0f, 1.0f + fex2(fmaf(vP.x, kP, C7L)));
    vP.y = __fdividef(1.0f, 1.0f + fex2(fmaf(vP.y, kP, C7L)));
    vP.z = __fdividef(1.0f, 1.0f + fex2(fmaf(vP.z, kP, C7L)));
    vP.w = __fdividef(1.0f, 1.0f + fex2(fmaf(vP.w, kP, C7L)));
    vG.x = __fdividef(1.0f, 1.0f + fex2(fmaf(vG.x, kG, C7L)));
    vG.y = __fdividef(1.0f, 1.0f + fex2(fmaf(vG.y, kG, C7L)));
    vG.z = __fdividef(1.0f, 1.0f + fex2(fmaf(vG.z, kG, C7L)));
    vG.w = __fdividef(1.0f, 1.0f + fex2(fmaf(vG.w, kG, C7L)));
    *bP = vP;
    *bG = vG;

    if (blockIdx.x == 0 && threadIdx.x == 0) {
        g_lm[lmP] = __fdividef(1.0f, 1.0f + fex2(fmaf(MP, kP, C7L)));
        g_lm[lmG] = __fdividef(1.0f, 1.0f + fex2(fmaf(MG, kG, C7L)));
    }
}

__global__ __launch_bounds__(256) void maxPG_kernel(
    const float* __restrict__ pred, const float* __restrict__ gt) {
    int t = blockIdx.x * 256 + threadIdx.x;
    float4 a = ((const float4*)pred)[t];
    float4 b = ((const float4*)gt)[t];
    float mP = fmaxf(fmaxf(a.x, a.y), fmaxf(a.z, a.w));
    float mG = fmaxf(fmaxf(b.x, b.y), fmaxf(b.z, b.w));
    blockReduceMax2(mP, mG);
    if (threadIdx.x == 0) {
        atomicMax((int*)&g_lm[0], __float_as_int(mP));
        atomicMax((int*)&g_lm[1], __float_as_int(mG));
    }
}

__global__ void init_kernel() {
    if (threadIdx.x == 0) {
        g_loss = 0.0;
#pragma unroll
        for (int i = 0; i < 4; ++i) g_cmax[i] = 0.0f;
#pragma unroll
        for (int i = 0; i < 6; ++i) g_lm[i] = 0.0f;
    }
}
__global__ void final_kernel(float* out) {
    out[0] = (float)(g_loss * (1.0 / (double)BATCH));
}

// ---------------- launch --------------------------------------------------
extern "C" void kernel_launch(void* const* d_in, const int* in_sizes, int n_in,
                              void* d_out, int out_size) {
    const float* pred = (const float*)d_in[0];
    const float* gt = (const float*)d_in[1];
    float* out = (float*)d_out;
    const int nb4 = NTOT / 1024;

    init_kernel<<<1, 32>>>();
    maxPG_kernel<<<nb4, 256>>>(pred, gt);

    erode_conv2_kernel<<<nb4, 256>>>(pred, gt, 0, 1, 0, 1, 0, 1);  // lvl0 -> P1,G1
    erode_norm2_kernel<<<nb4, 256>>>(0, 1, 0, 1, 2, 3);
    erode_conv2_kernel<<<nb4, 256>>>(pred, gt, 2, 3, 2, 3, 2, 3);  // lvl1 -> P2,G2
    erode_norm2_kernel<<<nb4, 256>>>(2, 3, 2, 3, 4, 5);

    dim3 grid(WW / 32, HH / 32, BATCH);
    for (int lvl = 0; lvl < 3; ++lvl) {
        int selP = (lvl == 0) ? 0 : (lvl == 1 ? 2 : 4);
        int selG = (lvl == 0) ? 1 : (lvl == 1 ? 3 : 5);
        cp_dual_kernel<<<grid, 256>>>(pred, gt, selP, selG, 2 * lvl, 2 * lvl + 1);
    }

    final_kernel<<<1, 1>>>(out);
}